// round 9
// baseline (speedup 1.0000x reference)
#include <cuda_runtime.h>
#include <cstdint>

// Problem constants
#define NPX      65536
#define KCODES   1024
#define DDIM     256
#define HW       4096
#define TILE_PX  64
#define TILE_K   64
#define NKT      (KCODES / TILE_K)   // 16
#define NTILES   (NPX / TILE_PX)     // 1024
#define ZQ_ELEMS 16777216

// Device scratch (allocation-free per harness rules)
__device__ float    g_cbT[DDIM * KCODES];   // transposed codebook [c][k]
__device__ float    g_esq[KCODES];
__device__ float    g_loss_acc;
__device__ unsigned g_done;

// smem layout (floats):
//   z_s   [256][64]            16384
//   e_s   2 x [256][64]        32768   (transposed chunk: [c][k], packed)
//   esq_s [1024]                1024
//   zsq_s [64]                    64
//   s_idx [64]                    64
//   swsum [8]                      8
#define ZS_F   (DDIM * TILE_PX)
#define EB_F   (DDIM * TILE_K)           // 16384 per buffer
#define SMEM_FLOATS (ZS_F + 2 * EB_F + 1024 + 64 + 64 + 8)   // 50312 = 201248 B

__device__ __forceinline__ uint32_t smem_u32(const void* p) {
    uint32_t a;
    asm("{ .reg .u64 t; cvta.to.shared.u64 t, %1; cvt.u32.u64 %0, t; }" : "=r"(a) : "l"(p));
    return a;
}
#define CP_ASYNC16(dst, src) \
    asm volatile("cp.async.cg.shared.global [%0], [%1], 16;" :: "r"(dst), "l"(src))
#define CP_COMMIT  asm volatile("cp.async.commit_group;")
#define CP_WAIT1   asm volatile("cp.async.wait_group 1;")
#define CP_WAIT0   asm volatile("cp.async.wait_group 0;")

// ---------------------------------------------------------------------------
// Prep: esq[k] via bit-exact sequential chain (loads batched into registers
// for MLP; FP order unchanged). Also resets loss accumulator and done counter.
// ---------------------------------------------------------------------------
__global__ void vq_prep(const float* __restrict__ cb) {
    int k = blockIdx.x * blockDim.x + threadIdx.x;
    if (k == 0) { g_loss_acc = 0.0f; g_done = 0u; }
    if (k < KCODES) {
        const float4* row = (const float4*)(cb + (size_t)k * DDIM);
        float s = 0.0f;
        #pragma unroll
        for (int bt = 0; bt < 8; bt++) {
            float4 buf[8];
            #pragma unroll
            for (int i = 0; i < 8; i++) buf[i] = row[bt * 8 + i];   // 8 LDG.128 in flight
            #pragma unroll
            for (int i = 0; i < 8; i++) {                           // exact chain order
                s = __fadd_rn(s, __fmul_rn(buf[i].x, buf[i].x));
                s = __fadd_rn(s, __fmul_rn(buf[i].y, buf[i].y));
                s = __fadd_rn(s, __fmul_rn(buf[i].z, buf[i].z));
                s = __fadd_rn(s, __fmul_rn(buf[i].w, buf[i].w));
            }
        }
        g_esq[k] = s;
    }
}

// ---------------------------------------------------------------------------
// Transpose codebook: cb[k][c] -> g_cbT[c][k]  (32x32 smem tiles)
// ---------------------------------------------------------------------------
__global__ void vq_tr(const float* __restrict__ cb) {
    __shared__ float ts[32][33];
    int k0 = blockIdx.x * 32, c0 = blockIdx.y * 32;
    int tx = threadIdx.x, ty = threadIdx.y;   // (32, 8)
    #pragma unroll
    for (int i = 0; i < 4; i++)
        ts[ty + 8 * i][tx] = cb[(size_t)(k0 + ty + 8 * i) * DDIM + c0 + tx];
    __syncthreads();
    #pragma unroll
    for (int i = 0; i < 4; i++)
        g_cbT[(size_t)(c0 + ty + 8 * i) * KCODES + k0 + tx] = ts[tx][ty + 8 * i];
}

// ---------------------------------------------------------------------------
// Main: fused distance-GEMM + argmin + z_q + loss, cp.async double-buffered
// codebook chunks ([c][k] layout: 16B-aligned AND conflict-free).
// ---------------------------------------------------------------------------
__global__ __launch_bounds__(256, 1)
void vq_main(const float* __restrict__ z, const float* __restrict__ cb,
             float* __restrict__ out_zq, float* __restrict__ out_idx,
             float* __restrict__ out) {
    extern __shared__ float smem[];
    float* z_s   = smem;
    float* e_s   = smem + ZS_F;                 // 2 buffers of EB_F
    float* esq_s = smem + ZS_F + 2 * EB_F;
    float* zsq_s = esq_s + 1024;
    int*   s_idx = (int*)(zsq_s + 64);
    float* swsum = zsq_s + 128;
    const uint32_t eb_addr = smem_u32(e_s);

    const int t  = threadIdx.x;
    const int tx = t & 31;        // code lane: codes {2tx, 2tx+1} per chunk
    const int ty = t >> 5;        // warp id == pixel group (8 px each)
    const int tile = blockIdx.x;            // 0..1023
    const int b    = tile >> 6;
    const int hw0  = (tile & 63) << 6;

    const float* zb = z + (size_t)b * (DDIM * HW) + hw0;

    // issue cp.async for e-chunk 0 (transposed: [c][64 codes], packed)
    {
        #pragma unroll
        for (int it = 0; it < 16; it++) {
            int task = it * 256 + t, c = task >> 4, seg = task & 15;
            CP_ASYNC16(eb_addr + (uint32_t)(c * TILE_K + seg * 4) * 4,
                       g_cbT + (size_t)c * KCODES + seg * 4);
        }
        CP_COMMIT;
    }

    // Load z tile [256 c][64 px] (coalesced) + esq -> smem
    #pragma unroll
    for (int r = 0; r < 16; r++) {
        int e  = r * 256 + t, c = e >> 4, f4 = e & 15;
        float4 v = ((const float4*)(zb + (size_t)c * HW))[f4];
        *((float4*)&z_s[c * TILE_PX + f4 * 4]) = v;
    }
    ((float4*)esq_s)[t] = ((const float4*)g_esq)[t];
    __syncthreads();

    // Per-pixel zsq (bit-exact sequential chain)
    if (t < TILE_PX) {
        float s = 0.0f;
        for (int c = 0; c < DDIM; c++) {
            float v = z_s[c * TILE_PX + t];
            s = __fadd_rn(s, __fmul_rn(v, v));
        }
        zsq_s[t] = s;
    }
    __syncthreads();

    float zsqr[8];
    #pragma unroll
    for (int i = 0; i < 8; i++) zsqr[i] = zsq_s[ty * 8 + i];

    float bestd[8];
    int   bestk[8];
    #pragma unroll
    for (int i = 0; i < 8; i++) { bestd[i] = 3.4e38f; bestk[i] = 0; }

    for (int kt = 0; kt < NKT; kt++) {
        if (kt + 1 < NKT) {
            // stage chunk kt+1 into the other buffer (no hazard: compute of
            // kt-1 on that buffer finished before last iteration's tail sync)
            const float* src = g_cbT + (kt + 1) * TILE_K;
            uint32_t dst = eb_addr + (uint32_t)(((kt + 1) & 1) * EB_F) * 4;
            #pragma unroll
            for (int it = 0; it < 16; it++) {
                int task = it * 256 + t, c = task >> 4, seg = task & 15;
                CP_ASYNC16(dst + (uint32_t)(c * TILE_K + seg * 4) * 4,
                           src + (size_t)c * KCODES + seg * 4);
            }
            CP_COMMIT;
            CP_WAIT1;      // chunk kt complete (kt+1 group still in flight)
        } else {
            CP_WAIT0;
        }
        __syncthreads();

        const float* eb = e_s + (kt & 1) * EB_F;
        float acc[8][2];
        #pragma unroll
        for (int i = 0; i < 8; i++) { acc[i][0] = 0.0f; acc[i][1] = 0.0f; }

        // dot products: 8 px x 2 adjacent codes per thread.
        // Single accumulator, ascending c, fused FMA (bit-exact ordering).
        #pragma unroll 8
        for (int c = 0; c < DDIM; c++) {
            float4 za  = *((const float4*)&z_s[c * TILE_PX + ty * 8]);      // broadcast
            float4 zb4 = *((const float4*)&z_s[c * TILE_PX + ty * 8 + 4]);  // broadcast
            float2 ev  = *((const float2*)&eb[c * TILE_K + 2 * tx]);        // LDS.64 cf
            float e0 = ev.x, e1 = ev.y;
            acc[0][0] = fmaf(za.x,  e0, acc[0][0]); acc[0][1] = fmaf(za.x,  e1, acc[0][1]);
            acc[1][0] = fmaf(za.y,  e0, acc[1][0]); acc[1][1] = fmaf(za.y,  e1, acc[1][1]);
            acc[2][0] = fmaf(za.z,  e0, acc[2][0]); acc[2][1] = fmaf(za.z,  e1, acc[2][1]);
            acc[3][0] = fmaf(za.w,  e0, acc[3][0]); acc[3][1] = fmaf(za.w,  e1, acc[3][1]);
            acc[4][0] = fmaf(zb4.x, e0, acc[4][0]); acc[4][1] = fmaf(zb4.x, e1, acc[4][1]);
            acc[5][0] = fmaf(zb4.y, e0, acc[5][0]); acc[5][1] = fmaf(zb4.y, e1, acc[5][1]);
            acc[6][0] = fmaf(zb4.z, e0, acc[6][0]); acc[6][1] = fmaf(zb4.z, e1, acc[6][1]);
            acc[7][0] = fmaf(zb4.w, e0, acc[7][0]); acc[7][1] = fmaf(zb4.w, e1, acc[7][1]);
        }

        // d = fl( fl(zsq + esq_k) - fl(2*dot) ); k ascending per thread
        #pragma unroll
        for (int j = 0; j < 2; j++) {
            int kg = kt * TILE_K + 2 * tx + j;
            float eq = esq_s[kg];
            #pragma unroll
            for (int i = 0; i < 8; i++) {
                float t1 = __fadd_rn(zsqr[i], eq);
                float d  = __fsub_rn(t1, __fmul_rn(2.0f, acc[i][j]));
                if (d < bestd[i]) { bestd[i] = d; bestk[i] = kg; }
            }
        }
        __syncthreads();   // all reads of buffer kt&1 done before it is refilled
    }

    // Full-warp butterfly min-reduce with lowest-index tie-break
    #pragma unroll
    for (int i = 0; i < 8; i++) {
        float d = bestd[i];
        int   k = bestk[i];
        #pragma unroll
        for (int off = 16; off >= 1; off >>= 1) {
            float od = __shfl_xor_sync(0xFFFFFFFFu, d, off);
            int   ok = __shfl_xor_sync(0xFFFFFFFFu, k, off);
            if (od < d || (od == d && ok < k)) { d = od; k = ok; }
        }
        if (tx == 0) s_idx[ty * 8 + i] = k;
    }
    __syncthreads();

    // Epilogue: straight-through z_q write (coalesced), loss partial, idx
    float lsum = 0.0f;
    float* out_base = out_zq + (size_t)b * (DDIM * HW) + hw0;
    #pragma unroll 4
    for (int r = 0; r < 64; r++) {
        int e  = r * 256 + t, c = e >> 6, px = e & 63;
        int kk = s_idx[px];
        float q  = __ldg(&cb[(size_t)kk * DDIM + c]);
        float zv = z_s[c * TILE_PX + px];
        float dd = __fsub_rn(q, zv);
        lsum = fmaf(dd, dd, lsum);
        out_base[(size_t)c * HW + px] = __fadd_rn(zv, dd);
    }
    if (t < TILE_PX) out_idx[(size_t)tile * TILE_PX + t] = (float)s_idx[t];

    // block loss reduce + last-block finalize (replaces vq_finalize kernel)
    #pragma unroll
    for (int off = 16; off >= 1; off >>= 1)
        lsum += __shfl_xor_sync(0xFFFFFFFFu, lsum, off);
    if ((t & 31) == 0) swsum[t >> 5] = lsum;
    __syncthreads();
    if (t == 0) {
        float bs = 0.0f;
        #pragma unroll
        for (int w = 0; w < 8; w++) bs += swsum[w];
        atomicAdd(&g_loss_acc, bs);
        __threadfence();
        unsigned n = atomicAdd(&g_done, 1u);
        if (n == NTILES - 1) {
            float m = __fmul_rn(g_loss_acc, 1.0f / (float)ZQ_ELEMS);
            out[ZQ_ELEMS + NPX] = __fmul_rn(1.25f, m);
        }
    }
}

extern "C" void kernel_launch(void* const* d_in, const int* in_sizes, int n_in,
                              void* d_out, int out_size) {
    const float* z  = (const float*)d_in[0];
    const float* cb = (const float*)d_in[1];
    float* out = (float*)d_out;
    float* out_zq  = out;
    float* out_idx = out + ZQ_ELEMS;

    vq_prep<<<16, 64>>>(cb);
    vq_tr<<<dim3(32, 8), dim3(32, 8)>>>(cb);

    size_t smem_bytes = SMEM_FLOATS * sizeof(float);
    cudaFuncSetAttribute(vq_main, cudaFuncAttributeMaxDynamicSharedMemorySize,
                         (int)smem_bytes);
    vq_main<<<NTILES, 256, smem_bytes>>>(z, cb, out_zq, out_idx, out);
}

// round 10
// speedup vs baseline: 1.0459x; 1.0459x over previous
#include <cuda_runtime.h>

// Problem constants
#define NPX      65536      // 16 * 64 * 64 pixels
#define KCODES   1024
#define DDIM     256
#define HW       4096       // 64*64
#define TILE_PX  64
#define TILE_K   128
#define NKT      (KCODES / TILE_K)   // 8
#define NTILES   (NPX / TILE_PX)     // 1024
#define ZQ_ELEMS 16777216   // 16*256*64*64

// Scratch (device globals; allocation-free per harness rules)
__device__ float    g_esq[KCODES];
__device__ float    g_loss_acc;
__device__ unsigned g_done;

// smem layout (floats):
//   z_s   [256][64]             16384
//   e_s   [128][257]            32896   (257 pad -> conflict-free compute reads)
//   esq_s [1024]                 1024
//   zsq_s [64]                     64
//   s_idx [64] (as int)            64
//   swsum [8]                       8
#define ZS_F   (DDIM * TILE_PX)          // 16384
#define ES_F   (TILE_K * 257)            // 32896
#define SMEM_FLOATS (ZS_F + ES_F + 1024 + 64 + 64 + 8)

// ---------------------------------------------------------------------------
// Prep: esq[k] = sequential fp32 sum of e_c^2 (mul then add) -- FP order is
// the bit-exact reference chain; loads are software-pipelined (batch bt+1
// fetched while batch bt is chained). Also resets loss/done for graph replay.
// ---------------------------------------------------------------------------
__global__ void vq_prep(const float* __restrict__ cb) {
    int k = blockIdx.x * blockDim.x + threadIdx.x;
    if (k == 0) { g_loss_acc = 0.0f; g_done = 0u; }
    if (k < KCODES) {
        const float4* row = (const float4*)(cb + (size_t)k * DDIM);
        float4 cur[8], nxt[8];
        #pragma unroll
        for (int i = 0; i < 8; i++) cur[i] = row[i];           // batch 0 in flight
        float s = 0.0f;
        #pragma unroll
        for (int bt = 0; bt < 8; bt++) {
            if (bt < 7) {
                #pragma unroll
                for (int i = 0; i < 8; i++) nxt[i] = row[(bt + 1) * 8 + i];
            }
            #pragma unroll
            for (int i = 0; i < 8; i++) {                      // exact chain order
                s = __fadd_rn(s, __fmul_rn(cur[i].x, cur[i].x));
                s = __fadd_rn(s, __fmul_rn(cur[i].y, cur[i].y));
                s = __fadd_rn(s, __fmul_rn(cur[i].z, cur[i].z));
                s = __fadd_rn(s, __fmul_rn(cur[i].w, cur[i].w));
            }
            if (bt < 7) {
                #pragma unroll
                for (int i = 0; i < 8; i++) cur[i] = nxt[i];
            }
        }
        g_esq[k] = s;
    }
}

// ---------------------------------------------------------------------------
// Main: fused distance-GEMM + argmin + z_q gather/write + loss partial.
// (Structure and numerics identical to the proven round-8 kernel; the only
// addition is the last-block loss finalize at the tail.)
// ---------------------------------------------------------------------------
__global__ __launch_bounds__(256, 1)
void vq_main(const float* __restrict__ z, const float* __restrict__ cb,
             float* __restrict__ out_zq, float* __restrict__ out_idx,
             float* __restrict__ out) {
    extern __shared__ float smem[];
    float* z_s   = smem;
    float* e_s   = smem + ZS_F;
    float* esq_s = smem + ZS_F + ES_F;
    float* zsq_s = smem + ZS_F + ES_F + 1024;
    int*   s_idx = (int*)(smem + ZS_F + ES_F + 1024 + 64);
    float* swsum = smem + ZS_F + ES_F + 1024 + 128;

    const int t  = threadIdx.x;
    const int tx = t & 31;        // code lane (32 codes x 4 groups)
    const int ty = t >> 5;        // warp id == pixel group (8 px each)
    const int tile = blockIdx.x;            // 0..1023
    const int b    = tile >> 6;             // batch index (64 tiles per batch)
    const int hw0  = (tile & 63) << 6;      // hw offset (contiguous 64 pixels)

    const float* zb = z + (size_t)b * (DDIM * HW) + hw0;

    // Load z tile [256 c][64 px] into smem (coalesced: hw is fast axis)
    #pragma unroll
    for (int r = 0; r < 16; r++) {
        int e  = r * 256 + t;     // float4 task id, 4096 total
        int c  = e >> 4;
        int f4 = e & 15;
        float4 v = ((const float4*)(zb + (size_t)c * HW))[f4];
        *((float4*)&z_s[c * TILE_PX + f4 * 4]) = v;
    }
    // esq -> smem (1024 floats = 256 float4)
    ((float4*)esq_s)[t] = ((const float4*)g_esq)[t];
    __syncthreads();

    // Per-pixel zsq: sequential fp32 sum of z_c^2 (mul then add, exact chain)
    if (t < TILE_PX) {
        float s = 0.0f;
        for (int c = 0; c < DDIM; c++) {
            float v = z_s[c * TILE_PX + t];
            s = __fadd_rn(s, __fmul_rn(v, v));
        }
        zsq_s[t] = s;
    }
    __syncthreads();

    float zsqr[8];
    #pragma unroll
    for (int i = 0; i < 8; i++) zsqr[i] = zsq_s[ty * 8 + i];

    float bestd[8];
    int   bestk[8];
    #pragma unroll
    for (int i = 0; i < 8; i++) { bestd[i] = 3.4e38f; bestk[i] = 0; }

    for (int kt = 0; kt < NKT; kt++) {
        if (kt) __syncthreads();
        // Load codebook tile [128 k][256 c] -> e_s[k*257 + c]
        const float* cbt = cb + (size_t)kt * TILE_K * DDIM;
        #pragma unroll
        for (int i = 0; i < 32; i++) {
            int e  = i * 256 + t;     // 8192 float4 tasks
            int k  = e >> 6;
            int c4 = e & 63;
            float4 v = ((const float4*)(cbt + k * DDIM))[c4];
            float* dst = &e_s[k * 257 + c4 * 4];
            dst[0] = v.x; dst[1] = v.y; dst[2] = v.z; dst[3] = v.w;
        }
        __syncthreads();

        float acc[8][4];
        #pragma unroll
        for (int i = 0; i < 8; i++)
            #pragma unroll
            for (int j = 0; j < 4; j++) acc[i][j] = 0.0f;

        // dot products: 8 px x 4 codes per thread.
        // Single accumulator per element, ascending c, fused FMA chain
        // (bit-identical to the proven round-2/8 ordering).
        #pragma unroll 8
        for (int c = 0; c < DDIM; c++) {
            float4 za  = *((const float4*)&z_s[c * TILE_PX + ty * 8]);      // broadcast
            float4 zb4 = *((const float4*)&z_s[c * TILE_PX + ty * 8 + 4]);  // broadcast
            float rz0 = za.x, rz1 = za.y, rz2 = za.z, rz3 = za.w;
            float rz4 = zb4.x, rz5 = zb4.y, rz6 = zb4.z, rz7 = zb4.w;
            float re[4];
            #pragma unroll
            for (int j = 0; j < 4; j++)
                re[j] = e_s[(tx + 32 * j) * 257 + c];   // conflict-free: bank = tx+c
            #pragma unroll
            for (int j = 0; j < 4; j++) {
                acc[0][j] = fmaf(rz0, re[j], acc[0][j]);
                acc[1][j] = fmaf(rz1, re[j], acc[1][j]);
                acc[2][j] = fmaf(rz2, re[j], acc[2][j]);
                acc[3][j] = fmaf(rz3, re[j], acc[3][j]);
                acc[4][j] = fmaf(rz4, re[j], acc[4][j]);
                acc[5][j] = fmaf(rz5, re[j], acc[5][j]);
                acc[6][j] = fmaf(rz6, re[j], acc[6][j]);
                acc[7][j] = fmaf(rz7, re[j], acc[7][j]);
            }
        }

        // d = fl( fl(zsq + esq_k) - fl(2*dot) )   -- exact reference rounding.
        // k visited ascending per thread -> strict < keeps first-min.
        #pragma unroll
        for (int j = 0; j < 4; j++) {
            int kg = kt * TILE_K + tx + 32 * j;
            float eq = esq_s[kg];
            #pragma unroll
            for (int i = 0; i < 8; i++) {
                float t1 = __fadd_rn(zsqr[i], eq);
                float d  = __fsub_rn(t1, __fmul_rn(2.0f, acc[i][j]));
                if (d < bestd[i]) { bestd[i] = d; bestk[i] = kg; }
            }
        }
    }

    // Full-warp butterfly min-reduce with lowest-index tie-break
    #pragma unroll
    for (int i = 0; i < 8; i++) {
        float d = bestd[i];
        int   k = bestk[i];
        #pragma unroll
        for (int off = 16; off >= 1; off >>= 1) {
            float od = __shfl_xor_sync(0xFFFFFFFFu, d, off);
            int   ok = __shfl_xor_sync(0xFFFFFFFFu, k, off);
            if (od < d || (od == d && ok < k)) { d = od; k = ok; }
        }
        if (tx == 0) s_idx[ty * 8 + i] = k;
    }
    __syncthreads();

    // Epilogue: straight-through z_q write (coalesced), loss partial, idx write
    float lsum = 0.0f;
    float* out_base = out_zq + (size_t)b * (DDIM * HW) + hw0;
    #pragma unroll 4
    for (int r = 0; r < 64; r++) {
        int e  = r * 256 + t;       // 16384 elements
        int c  = e >> 6;
        int px = e & 63;
        int kk = s_idx[px];
        float q  = __ldg(&cb[(size_t)kk * DDIM + c]);
        float zv = z_s[c * TILE_PX + px];
        float dd = __fsub_rn(q, zv);                 // z_q - z
        lsum = fmaf(dd, dd, lsum);                   // loss partial
        out_base[(size_t)c * HW + px] = __fadd_rn(zv, dd);  // z + (z_q - z)
    }
    if (t < TILE_PX) out_idx[(size_t)tile * TILE_PX + t] = (float)s_idx[t];

    // block loss reduce + last-block finalize (replaces vq_finalize launch)
    #pragma unroll
    for (int off = 16; off >= 1; off >>= 1)
        lsum += __shfl_xor_sync(0xFFFFFFFFu, lsum, off);
    if ((t & 31) == 0) swsum[t >> 5] = lsum;
    __syncthreads();
    if (t == 0) {
        float bs = 0.0f;
        #pragma unroll
        for (int w = 0; w < 8; w++) bs += swsum[w];
        atomicAdd(&g_loss_acc, bs);
        __threadfence();
        unsigned n = atomicAdd(&g_done, 1u);
        if (n == NTILES - 1) {
            float m = __fmul_rn(g_loss_acc, 1.0f / (float)ZQ_ELEMS);  // /2^24 exact
            out[ZQ_ELEMS + NPX] = __fmul_rn(1.25f, m);
        }
    }
}

extern "C" void kernel_launch(void* const* d_in, const int* in_sizes, int n_in,
                              void* d_out, int out_size) {
    const float* z  = (const float*)d_in[0];
    const float* cb = (const float*)d_in[1];
    float* out = (float*)d_out;

    // out layout: [z_q: 16777216][idx: 65536][loss: 1]
    float* out_zq  = out;
    float* out_idx = out + ZQ_ELEMS;

    vq_prep<<<64, 16>>>(cb);

    size_t smem_bytes = SMEM_FLOATS * sizeof(float);
    cudaFuncSetAttribute(vq_main, cudaFuncAttributeMaxDynamicSharedMemorySize,
                         (int)smem_bytes);
    vq_main<<<NTILES, 256, smem_bytes>>>(z, cb, out_zq, out_idx, out);
}